// round 11
// baseline (speedup 1.0000x reference)
#include <cuda_runtime.h>
#include <cuda_fp16.h>
#include <cstdint>
#include <cstddef>

// ============================================================================
// proj[b,c] = sum_{i,j} t[b,i] * W[c, i*512+j] * f[b,j]   (B=2048, F=512, C=64)
// out = relu(relu(proj + bp) @ W1^T + b1) @ W2^T + b2
//
// fp16 mma.sync.m16n8k16. R10: channel-group CTAs — A tile (128x512) and f tile
// resident in smem, reused across G=4 channels. L2 traffic 1.34GB -> 0.74GB.
// B streamed via direct LDG (ring-4 regs, prefetch distance 2). No mainloop
// syncthreads. 1024 CTAs, 1 CTA/SM (194KB smem).
// ============================================================================

// g_T [bt256(8)][kc16(32)][mt(16)][lane(32)][4 u32]     (2 MB)
// g_W [c(64)][jt(4)][kc16(32)][nt(16)][lane(32)][2 u32] (33.5 MB)
__device__ uint32_t g_T[8 * 32 * 16 * 32 * 4];
__device__ uint32_t g_W[64 * 4 * 32 * 16 * 32 * 2];
__device__ float    g_partial[16 * 2048 * 64];

// ---------------- helpers ----------------
__device__ __forceinline__ uint32_t packh2(float lo, float hi) {
    __half2 h = __floats2half2_rn(lo, hi);
    return *(uint32_t*)&h;
}
__device__ __forceinline__ void cp16(uint32_t dst_smem, const void* src) {
    asm volatile("cp.async.cg.shared.global [%0], [%1], 16;" :: "r"(dst_smem), "l"(src));
}
__device__ __forceinline__ void cp_commit() {
    asm volatile("cp.async.commit_group;" ::: "memory");
}
__device__ __forceinline__ void mma_f16(float* d, const uint32_t* a, const uint32_t* b) {
    asm volatile(
        "mma.sync.aligned.m16n8k16.row.col.f32.f16.f16.f32 "
        "{%0,%1,%2,%3},{%4,%5,%6,%7},{%8,%9},{%0,%1,%2,%3};"
        : "+f"(d[0]), "+f"(d[1]), "+f"(d[2]), "+f"(d[3])
        : "r"(a[0]), "r"(a[1]), "r"(a[2]), "r"(a[3]), "r"(b[0]), "r"(b[1]));
}

// ---------------- conv (unchanged: fragment-order fp16) ----------------
__global__ void conv_kernel(const float* __restrict__ t, const float* __restrict__ W) {
    if (blockIdx.x < 2048) {
        __shared__ float ws[64 * 132];
        int b = blockIdx.x;
        int c = b >> 5, jt = (b >> 3) & 3, ktile = b & 7;
        int tid = threadIdx.x, lane = tid & 31, warp = tid >> 5;

        const float* src = W + (size_t)c * 262144 + (size_t)(ktile * 64) * 512 + jt * 128;
#pragma unroll
        for (int r = 0; r < 8; r++) {
            int k = r * 8 + warp;
            float4 v = *(const float4*)&src[(size_t)k * 512 + lane * 4];
            float* d = &ws[k * 132 + lane * 4];
            d[0] = v.x; d[1] = v.y; d[2] = v.z; d[3] = v.w;
        }
        __syncthreads();

#pragma unroll
        for (int i = 0; i < 8; i++) {
            int p = warp * 8 + i;
            int q = p >> 4, nt = p & 15;
            int k0 = q * 16 + (lane & 3) * 2;
            int n  = nt * 8 + (lane >> 2);
            uint32_t v0 = packh2(ws[k0 * 132 + n],       ws[(k0 + 1) * 132 + n]);
            uint32_t v1 = packh2(ws[(k0 + 8) * 132 + n], ws[(k0 + 9) * 132 + n]);
            size_t base = ((size_t)((c * 4 + jt) * 32 + ktile * 4 + q) * 16 + nt) * 64 + lane * 2;
            *(uint2*)&g_W[base] = make_uint2(v0, v1);
        }
    } else {
        int gid = (blockIdx.x - 2048) * 256 + threadIdx.x;
        int lane  = gid & 31;
        int mt    = (gid >> 5) & 15;
        int kc    = (gid >> 9) & 31;
        int btile = gid >> 14;
        int row = btile * 256 + mt * 16 + (lane >> 2);
        int k0  = kc * 16 + (lane & 3) * 2;
        float2 p00 = *(const float2*)&t[(size_t)row * 512 + k0];
        float2 p10 = *(const float2*)&t[(size_t)(row + 8) * 512 + k0];
        float2 p01 = *(const float2*)&t[(size_t)row * 512 + k0 + 8];
        float2 p11 = *(const float2*)&t[(size_t)(row + 8) * 512 + k0 + 8];
        *(uint4*)&g_T[(size_t)gid * 4] =
            make_uint4(packh2(p00.x, p00.y), packh2(p10.x, p10.y),
                       packh2(p01.x, p01.y), packh2(p11.x, p11.y));
    }
}

// ---------------- GEMM + f-dot epilogue ----------------
// CTA: 128(m) x 128(n) x G=4 channels. 8 warps: mw=warp&1 (64 rows), nw=warp>>1 (32 cols).
// smem: A resident [0,131072) = 32 slabs of 4KB (kc-major, fragment order);
//       f resident [131072, 131072+128*132*4).
static constexpr int G = 4;
static constexpr uint32_t SMEM_A  = 131072;
static constexpr uint32_t SMEM_F  = 128 * 132 * 4;       // 67584
static constexpr uint32_t SMEM_GEMM = SMEM_A + SMEM_F;   // 198656

__global__ __launch_bounds__(256, 1) void gemm_kernel(const float* __restrict__ f_feat) {
    extern __shared__ __align__(16) unsigned char smem_dyn[];
    uint32_t* smem = (uint32_t*)smem_dyn;
    int tid = threadIdx.x;
    int lane = tid & 31, warp = tid >> 5;
    int mw = warp & 1, nw = warp >> 1;
    int btile = blockIdx.x, jt = blockIdx.y, c0 = blockIdx.z * G;

    const char* gA = (const char*)g_T + (size_t)(btile >> 1) * 32 * 8192 + (btile & 1) * 4096;
    uint32_t sbase = (uint32_t)__cvta_generic_to_shared(smem);

    // --- prologue: A in 4 cp.async groups of 8 slabs, then f as group 5 ---
#pragma unroll
    for (int g = 0; g < 4; g++) {
#pragma unroll
        for (int s = 0; s < 8; s++) {
            int slab = g * 8 + s;
            cp16(sbase + slab * 4096 + tid * 16, gA + (size_t)slab * 8192 + tid * 16);
        }
        cp_commit();
    }
    const float* fsrc = f_feat + (size_t)(btile * 128) * 512 + jt * 128;
#pragma unroll
    for (int k = 0; k < 16; k++) {
        int i = k * 256 + tid;
        int row = i >> 5, cg = i & 31;
        cp16(sbase + SMEM_A + row * 528 + cg * 16, fsrc + (size_t)row * 512 + cg * 4);
    }
    cp_commit();

    float acc[4][4][4];
#pragma unroll
    for (int mt = 0; mt < 4; mt++)
#pragma unroll
        for (int nt = 0; nt < 4; nt++)
#pragma unroll
            for (int q = 0; q < 4; q++) acc[mt][nt][q] = 0.f;

    // B: uint2 fragment stream, ring-4 buffers, prefetch distance 2.
    const uint2* __restrict__ gB = (const uint2*)g_W;
    const size_t B0 = ((size_t)(c0 * 4 + jt) * 32) * 512 + nw * 128 + lane;
    uint2 breg[4][4];
#pragma unroll
    for (int nt = 0; nt < 4; nt++) breg[0][nt] = gB[B0 + nt * 32];
#pragma unroll
    for (int nt = 0; nt < 4; nt++) breg[1][nt] = gB[B0 + 512 + nt * 32];

    const uint32_t* sA = smem;
    float* fs = (float*)(smem_dyn + SMEM_A);

    for (int ci = 0; ci < G; ci++) {
        for (int kc4 = 0; kc4 < 8; kc4++) {
            if (ci == 0 && (kc4 & 1) == 0) {
                switch (kc4 >> 1) {
                    case 0: asm volatile("cp.async.wait_group 4;" ::: "memory"); break;
                    case 1: asm volatile("cp.async.wait_group 3;" ::: "memory"); break;
                    case 2: asm volatile("cp.async.wait_group 2;" ::: "memory"); break;
                    default: asm volatile("cp.async.wait_group 1;" ::: "memory"); break;
                }
                __syncthreads();
            }
#pragma unroll
            for (int u = 0; u < 4; u++) {
                int step = ci * 32 + kc4 * 4 + u;
                int sp = step + 2;
                if (sp < G * 32) {
                    size_t bi = B0 + (size_t)(sp >> 5) * 65536 + (size_t)(sp & 31) * 512;
#pragma unroll
                    for (int nt = 0; nt < 4; nt++)
                        breg[(u + 2) & 3][nt] = gB[bi + nt * 32];
                }
                int kc = kc4 * 4 + u;
                const uint32_t* pA = sA + (size_t)kc * 1024;
                uint4 aa[4];
#pragma unroll
                for (int mt = 0; mt < 4; mt++)
                    aa[mt] = *(const uint4*)&pA[((mw * 4 + mt) * 32 + lane) * 4];
#pragma unroll
                for (int mt = 0; mt < 4; mt++) {
                    uint32_t afr[4] = {aa[mt].x, aa[mt].y, aa[mt].z, aa[mt].w};
#pragma unroll
                    for (int nt = 0; nt < 4; nt++)
                        mma_f16(acc[mt][nt], afr, (const uint32_t*)&breg[u & 3][nt]);
                }
            }
        }

        // ---- epilogue for channel c0+ci (f resident; acc private; no syncs) ----
        if (ci == 0) {
            asm volatile("cp.async.wait_group 0;" ::: "memory");
            __syncthreads();
        }
        int c = c0 + ci;
#pragma unroll
        for (int mt = 0; mt < 4; mt++) {
#pragma unroll
            for (int h = 0; h < 2; h++) {
                int fl = mw * 64 + mt * 16 + (lane >> 2) + 8 * h;   // local row 0..127
                float sum = 0.f;
#pragma unroll
                for (int nt = 0; nt < 4; nt++) {
                    float2 fv = *(const float2*)&fs[fl * 132 + nw * 32 + nt * 8 + 2 * (lane & 3)];
                    sum = fmaf(acc[mt][nt][h * 2], fv.x, sum);
                    sum = fmaf(acc[mt][nt][h * 2 + 1], fv.y, sum);
                }
                sum += __shfl_xor_sync(0xffffffffu, sum, 1);
                sum += __shfl_xor_sync(0xffffffffu, sum, 2);
                if ((lane & 3) == 0) {
                    int bb = btile * 128 + fl;
                    g_partial[(size_t)(jt * 4 + nw) * 131072 + (size_t)bb * 64 + c] = sum;
                }
            }
        }
#pragma unroll
        for (int mt = 0; mt < 4; mt++)
#pragma unroll
            for (int nt = 0; nt < 4; nt++)
#pragma unroll
                for (int q = 0; q < 4; q++) acc[mt][nt][q] = 0.f;
    }
}

// ---------------- MLP: sum 16 slices + bias + relu + 64->32->1 ----------------
__global__ void mlp_kernel(const float* __restrict__ b_proj, const float* __restrict__ W1,
                           const float* __restrict__ b1, const float* __restrict__ W2,
                           const float* __restrict__ b2, float* __restrict__ out) {
    __shared__ float sW1[2048], sb1[32], sW2[32], sbp[64];
    int tid = threadIdx.x;
    for (int i = tid; i < 2048; i += 32) sW1[i] = W1[i];
    if (tid < 32) { sb1[tid] = b1[tid]; sW2[tid] = W2[tid]; }
    for (int i = tid; i < 64; i += 32) sbp[i] = b_proj[i];
    __syncthreads();

    int b = blockIdx.x * 32 + tid;
    float h[64];
#pragma unroll
    for (int cg = 0; cg < 16; cg++) {
        float4 v = *(const float4*)&g_partial[(size_t)b * 64 + cg * 4];
#pragma unroll
        for (int s = 1; s < 16; s++) {
            float4 p = *(const float4*)&g_partial[(size_t)s * 131072 + (size_t)b * 64 + cg * 4];
            v.x += p.x; v.y += p.y; v.z += p.z; v.w += p.w;
        }
        h[cg * 4 + 0] = fmaxf(v.x + sbp[cg * 4 + 0], 0.f);
        h[cg * 4 + 1] = fmaxf(v.y + sbp[cg * 4 + 1], 0.f);
        h[cg * 4 + 2] = fmaxf(v.z + sbp[cg * 4 + 2], 0.f);
        h[cg * 4 + 3] = fmaxf(v.w + sbp[cg * 4 + 3], 0.f);
    }
    float logit = b2[0];
#pragma unroll
    for (int k = 0; k < 32; k++) {
        float a = sb1[k];
#pragma unroll
        for (int cc = 0; cc < 64; cc++)
            a = fmaf(h[cc], sW1[k * 64 + cc], a);
        logit = fmaf(fmaxf(a, 0.f), sW2[k], logit);
    }
    out[b] = logit;
}

// ---------------- launcher ----------------
extern "C" void kernel_launch(void* const* d_in, const int* in_sizes, int n_in,
                              void* d_out, int out_size) {
    const float* t_feat = (const float*)d_in[0];
    const float* f_feat = (const float*)d_in[1];
    const float* W_proj = (const float*)d_in[2];
    const float* b_proj = (const float*)d_in[3];
    const float* W1     = (const float*)d_in[4];
    const float* b1     = (const float*)d_in[5];
    const float* W2     = (const float*)d_in[6];
    const float* b2     = (const float*)d_in[7];
    float* out = (float*)d_out;

    cudaFuncSetAttribute(gemm_kernel, cudaFuncAttributeMaxDynamicSharedMemorySize, SMEM_GEMM);

    conv_kernel<<<2560, 256>>>(t_feat, W_proj);
    dim3 grid(16, 4, 16);   // (btile, jt, c-group) = 1024 CTAs, 6.9 waves
    gemm_kernel<<<grid, 256, SMEM_GEMM>>>(f_feat);
    mlp_kernel<<<64, 32>>>(b_proj, W1, b1, W2, b2, out);
}

// round 12
// speedup vs baseline: 1.0519x; 1.0519x over previous
#include <cuda_runtime.h>
#include <cuda_fp16.h>
#include <cstdint>
#include <cstddef>

// ============================================================================
// proj[b,c] = sum_{i,j} t[b,i] * W[c, i*512+j] * f[b,j]   (B=2048, F=512, C=64)
// out = relu(relu(proj + bp) @ W1^T + b1) @ W2^T + b2
//
// fp16 mma.sync.m16n8k16. R11: channel-group CTA (A + f resident in smem,
// reused across G=4 channels => 0.74GB L2 traffic) with 512 threads / 16
// warps => 4 warps/SMSP (the TLP that R10's 256-thread version lost).
// Warp tile 32x32, acc 32 regs. B streamed direct-LDG, ring-4, distance 2.
// ============================================================================

// g_T [bt256(8)][kc16(32)][mt(16)][lane(32)][4 u32]     (2 MB)
// g_W [c(64)][jt(4)][kc16(32)][nt(16)][lane(32)][2 u32] (33.5 MB)
__device__ uint32_t g_T[8 * 32 * 16 * 32 * 4];
__device__ uint32_t g_W[64 * 4 * 32 * 16 * 32 * 2];
__device__ float    g_partial[16 * 2048 * 64];

// ---------------- helpers ----------------
__device__ __forceinline__ uint32_t packh2(float lo, float hi) {
    __half2 h = __floats2half2_rn(lo, hi);
    return *(uint32_t*)&h;
}
__device__ __forceinline__ void cp16(uint32_t dst_smem, const void* src) {
    asm volatile("cp.async.cg.shared.global [%0], [%1], 16;" :: "r"(dst_smem), "l"(src));
}
__device__ __forceinline__ void cp_commit() {
    asm volatile("cp.async.commit_group;" ::: "memory");
}
__device__ __forceinline__ void mma_f16(float* d, const uint32_t* a, const uint32_t* b) {
    asm volatile(
        "mma.sync.aligned.m16n8k16.row.col.f32.f16.f16.f32 "
        "{%0,%1,%2,%3},{%4,%5,%6,%7},{%8,%9},{%0,%1,%2,%3};"
        : "+f"(d[0]), "+f"(d[1]), "+f"(d[2]), "+f"(d[3])
        : "r"(a[0]), "r"(a[1]), "r"(a[2]), "r"(a[3]), "r"(b[0]), "r"(b[1]));
}

// ---------------- conv (unchanged: fragment-order fp16) ----------------
__global__ void conv_kernel(const float* __restrict__ t, const float* __restrict__ W) {
    if (blockIdx.x < 2048) {
        __shared__ float ws[64 * 132];
        int b = blockIdx.x;
        int c = b >> 5, jt = (b >> 3) & 3, ktile = b & 7;
        int tid = threadIdx.x, lane = tid & 31, warp = tid >> 5;

        const float* src = W + (size_t)c * 262144 + (size_t)(ktile * 64) * 512 + jt * 128;
#pragma unroll
        for (int r = 0; r < 8; r++) {
            int k = r * 8 + warp;
            float4 v = *(const float4*)&src[(size_t)k * 512 + lane * 4];
            float* d = &ws[k * 132 + lane * 4];
            d[0] = v.x; d[1] = v.y; d[2] = v.z; d[3] = v.w;
        }
        __syncthreads();

#pragma unroll
        for (int i = 0; i < 8; i++) {
            int p = warp * 8 + i;
            int q = p >> 4, nt = p & 15;
            int k0 = q * 16 + (lane & 3) * 2;
            int n  = nt * 8 + (lane >> 2);
            uint32_t v0 = packh2(ws[k0 * 132 + n],       ws[(k0 + 1) * 132 + n]);
            uint32_t v1 = packh2(ws[(k0 + 8) * 132 + n], ws[(k0 + 9) * 132 + n]);
            size_t base = ((size_t)((c * 4 + jt) * 32 + ktile * 4 + q) * 16 + nt) * 64 + lane * 2;
            *(uint2*)&g_W[base] = make_uint2(v0, v1);
        }
    } else {
        int gid = (blockIdx.x - 2048) * 256 + threadIdx.x;
        int lane  = gid & 31;
        int mt    = (gid >> 5) & 15;
        int kc    = (gid >> 9) & 31;
        int btile = gid >> 14;
        int row = btile * 256 + mt * 16 + (lane >> 2);
        int k0  = kc * 16 + (lane & 3) * 2;
        float2 p00 = *(const float2*)&t[(size_t)row * 512 + k0];
        float2 p10 = *(const float2*)&t[(size_t)(row + 8) * 512 + k0];
        float2 p01 = *(const float2*)&t[(size_t)row * 512 + k0 + 8];
        float2 p11 = *(const float2*)&t[(size_t)(row + 8) * 512 + k0 + 8];
        *(uint4*)&g_T[(size_t)gid * 4] =
            make_uint4(packh2(p00.x, p00.y), packh2(p10.x, p10.y),
                       packh2(p01.x, p01.y), packh2(p11.x, p11.y));
    }
}

// ---------------- GEMM + f-dot epilogue ----------------
// CTA: 128(m) x 128(n) x G=4 channels, 512 threads / 16 warps.
// mw = warp&3 (32 rows), nw = warp>>2 (32 cols). acc[2][4][4] = 32 regs.
// smem: A resident [0,131072) = 32 slabs of 4KB (kc-major, fragment order);
//       f resident [131072, +67584).
static constexpr int G = 4;
static constexpr uint32_t SMEM_A  = 131072;
static constexpr uint32_t SMEM_F  = 128 * 132 * 4;       // 67584
static constexpr uint32_t SMEM_GEMM = SMEM_A + SMEM_F;   // 198656

__global__ __launch_bounds__(512, 1) void gemm_kernel(const float* __restrict__ f_feat) {
    extern __shared__ __align__(16) unsigned char smem_dyn[];
    uint32_t* smem = (uint32_t*)smem_dyn;
    int tid = threadIdx.x;
    int lane = tid & 31, warp = tid >> 5;
    int mw = warp & 3, nw = warp >> 2;
    int btile = blockIdx.x, jt = blockIdx.y, c0 = blockIdx.z * G;

    const char* gA = (const char*)g_T + (size_t)(btile >> 1) * 32 * 8192 + (btile & 1) * 4096;
    uint32_t sbase = (uint32_t)__cvta_generic_to_shared(smem);

    // --- prologue: A in 4 cp.async groups (8 slabs each), then f as group 5 ---
    int half = tid >> 8;             // 0/1: which slab of the pair
    int toff = (tid & 255) * 16;
#pragma unroll
    for (int g = 0; g < 4; g++) {
#pragma unroll
        for (int i = 0; i < 4; i++) {
            int slab = g * 8 + i * 2 + half;
            cp16(sbase + slab * 4096 + toff, gA + (size_t)slab * 8192 + toff);
        }
        cp_commit();
    }
    const float* fsrc = f_feat + (size_t)(btile * 128) * 512 + jt * 128;
#pragma unroll
    for (int k = 0; k < 8; k++) {
        int i = k * 512 + tid;
        int row = i >> 5, cg = i & 31;
        cp16(sbase + SMEM_A + row * 528 + cg * 16, fsrc + (size_t)row * 512 + cg * 4);
    }
    cp_commit();

    float acc[2][4][4];
#pragma unroll
    for (int mt = 0; mt < 2; mt++)
#pragma unroll
        for (int nt = 0; nt < 4; nt++)
#pragma unroll
            for (int q = 0; q < 4; q++) acc[mt][nt][q] = 0.f;

    // B: uint2 fragment stream, ring-4 buffers, prefetch distance 2.
    const uint2* __restrict__ gB = (const uint2*)g_W;
    const size_t B0 = ((size_t)(c0 * 4 + jt) * 32) * 512 + (nw * 4) * 32 + lane;
    uint2 breg[4][4];
#pragma unroll
    for (int nt = 0; nt < 4; nt++) breg[0][nt] = gB[B0 + nt * 32];
#pragma unroll
    for (int nt = 0; nt < 4; nt++) breg[1][nt] = gB[B0 + 512 + nt * 32];

    const uint32_t* sA = smem;
    float* fs = (float*)(smem_dyn + SMEM_A);

    for (int ci = 0; ci < G; ci++) {
        for (int kc4 = 0; kc4 < 8; kc4++) {
            if (ci == 0 && (kc4 & 1) == 0) {
                switch (kc4 >> 1) {
                    case 0: asm volatile("cp.async.wait_group 4;" ::: "memory"); break;
                    case 1: asm volatile("cp.async.wait_group 3;" ::: "memory"); break;
                    case 2: asm volatile("cp.async.wait_group 2;" ::: "memory"); break;
                    default: asm volatile("cp.async.wait_group 1;" ::: "memory"); break;
                }
                __syncthreads();
            }
#pragma unroll
            for (int u = 0; u < 4; u++) {
                int step = ci * 32 + kc4 * 4 + u;
                int sp = step + 2;
                if (sp < G * 32) {
                    size_t bi = B0 + (size_t)(sp >> 5) * 65536 + (size_t)(sp & 31) * 512;
#pragma unroll
                    for (int nt = 0; nt < 4; nt++)
                        breg[(u + 2) & 3][nt] = gB[bi + nt * 32];
                }
                int kc = kc4 * 4 + u;
                const uint32_t* pA = sA + (size_t)kc * 1024;
                uint4 aa[2];
#pragma unroll
                for (int mt = 0; mt < 2; mt++)
                    aa[mt] = *(const uint4*)&pA[((mw * 2 + mt) * 32 + lane) * 4];
#pragma unroll
                for (int mt = 0; mt < 2; mt++) {
                    uint32_t afr[4] = {aa[mt].x, aa[mt].y, aa[mt].z, aa[mt].w};
#pragma unroll
                    for (int nt = 0; nt < 4; nt++)
                        mma_f16(acc[mt][nt], afr, (const uint32_t*)&breg[u & 3][nt]);
                }
            }
        }

        // ---- epilogue for channel c0+ci (f resident; acc private; no syncs) ----
        if (ci == 0) {
            asm volatile("cp.async.wait_group 0;" ::: "memory");
            __syncthreads();
        }
        int c = c0 + ci;
#pragma unroll
        for (int mt = 0; mt < 2; mt++) {
#pragma unroll
            for (int h = 0; h < 2; h++) {
                int fl = mw * 32 + mt * 16 + (lane >> 2) + 8 * h;   // local row 0..127
                float sum = 0.f;
#pragma unroll
                for (int nt = 0; nt < 4; nt++) {
                    float2 fv = *(const float2*)&fs[fl * 132 + nw * 32 + nt * 8 + 2 * (lane & 3)];
                    sum = fmaf(acc[mt][nt][h * 2], fv.x, sum);
                    sum = fmaf(acc[mt][nt][h * 2 + 1], fv.y, sum);
                }
                sum += __shfl_xor_sync(0xffffffffu, sum, 1);
                sum += __shfl_xor_sync(0xffffffffu, sum, 2);
                if ((lane & 3) == 0) {
                    int bb = btile * 128 + fl;
                    g_partial[(size_t)(jt * 4 + nw) * 131072 + (size_t)bb * 64 + c] = sum;
                }
            }
        }
#pragma unroll
        for (int mt = 0; mt < 2; mt++)
#pragma unroll
            for (int nt = 0; nt < 4; nt++)
#pragma unroll
                for (int q = 0; q < 4; q++) acc[mt][nt][q] = 0.f;
    }
}

// ---------------- MLP: sum 16 slices + bias + relu + 64->32->1 ----------------
__global__ void mlp_kernel(const float* __restrict__ b_proj, const float* __restrict__ W1,
                           const float* __restrict__ b1, const float* __restrict__ W2,
                           const float* __restrict__ b2, float* __restrict__ out) {
    __shared__ float sW1[2048], sb1[32], sW2[32], sbp[64];
    int tid = threadIdx.x;
    for (int i = tid; i < 2048; i += 32) sW1[i] = W1[i];
    if (tid < 32) { sb1[tid] = b1[tid]; sW2[tid] = W2[tid]; }
    for (int i = tid; i < 64; i += 32) sbp[i] = b_proj[i];
    __syncthreads();

    int b = blockIdx.x * 32 + tid;
    float h[64];
#pragma unroll
    for (int cg = 0; cg < 16; cg++) {
        float4 v = *(const float4*)&g_partial[(size_t)b * 64 + cg * 4];
#pragma unroll
        for (int s = 1; s < 16; s++) {
            float4 p = *(const float4*)&g_partial[(size_t)s * 131072 + (size_t)b * 64 + cg * 4];
            v.x += p.x; v.y += p.y; v.z += p.z; v.w += p.w;
        }
        h[cg * 4 + 0] = fmaxf(v.x + sbp[cg * 4 + 0], 0.f);
        h[cg * 4 + 1] = fmaxf(v.y + sbp[cg * 4 + 1], 0.f);
        h[cg * 4 + 2] = fmaxf(v.z + sbp[cg * 4 + 2], 0.f);
        h[cg * 4 + 3] = fmaxf(v.w + sbp[cg * 4 + 3], 0.f);
    }
    float logit = b2[0];
#pragma unroll
    for (int k = 0; k < 32; k++) {
        float a = sb1[k];
#pragma unroll
        for (int cc = 0; cc < 64; cc++)
            a = fmaf(h[cc], sW1[k * 64 + cc], a);
        logit = fmaf(fmaxf(a, 0.f), sW2[k], logit);
    }
    out[b] = logit;
}

// ---------------- launcher ----------------
extern "C" void kernel_launch(void* const* d_in, const int* in_sizes, int n_in,
                              void* d_out, int out_size) {
    const float* t_feat = (const float*)d_in[0];
    const float* f_feat = (const float*)d_in[1];
    const float* W_proj = (const float*)d_in[2];
    const float* b_proj = (const float*)d_in[3];
    const float* W1     = (const float*)d_in[4];
    const float* b1     = (const float*)d_in[5];
    const float* W2     = (const float*)d_in[6];
    const float* b2     = (const float*)d_in[7];
    float* out = (float*)d_out;

    cudaFuncSetAttribute(gemm_kernel, cudaFuncAttributeMaxDynamicSharedMemorySize, SMEM_GEMM);

    conv_kernel<<<2560, 256>>>(t_feat, W_proj);
    dim3 grid(16, 4, 16);   // (btile, jt, c-group) = 1024 CTAs, 6.9 waves
    gemm_kernel<<<grid, 512, SMEM_GEMM>>>(f_feat);
    mlp_kernel<<<64, 32>>>(b_proj, W1, b1, W2, b2, out);
}